// round 15
// baseline (speedup 1.0000x reference)
#include <cuda_runtime.h>

#define HID 4096
#define GATES (3*HID)
#define NVOCAB 256
#define ROWS_PER_BLOCK 8     // 8 warps, warp-per-row
#define MV1_GBLKS 8          // mv1: blocks 0-7 compute gate0 slices
#define MV1_WORKERS (GATES / ROWS_PER_BLOCK)   // 1536 worker blocks
#define DEC_WORKERS 32       // dec: blocks 0-31 decoder rows
#define DEC_GATES 8          // dec: blocks 32-39 gate1 slices

// Scratch (allocation-free rule: __device__ globals). 16B-aligned for float4.
__device__ __align__(16) float g_gi0[GATES];
__device__ __align__(16) float g_gh0[GATES];
__device__ __align__(16) float g_gh1[GATES];
__device__ __align__(16) float g_gi1[GATES];
__device__ __align__(16) float g_h0[HID];
__device__ __align__(16) float g_h1[HID];
// Replay-safe monotonic counters (never reset; epochs via division).
__device__ unsigned long long g_done0;   // +8 per replay   (mv1 gate blocks)
__device__ unsigned long long g_warr0;   // +1536 per replay (mv1 worker tickets)
__device__ unsigned long long g_done1;   // +8 per replay   (dec gate blocks)
__device__ unsigned long long g_warr1;   // +32 per replay  (dec worker tickets)

__device__ __forceinline__ float sigmoidf_(float v) {
    return __fdividef(1.0f, 1.0f + __expf(-v));
}
__device__ __forceinline__ float tanhf_(float v) {
    return __fdividef(2.0f, 1.0f + __expf(-2.0f * v)) - 1.0f;
}

// Prefetch this warp's 16KB weight row into L2 (4 x 128B lines per lane).
__device__ __forceinline__ void prefetch_row_l2(const float* wrow, int lane) {
    const char* p = (const char*)wrow;
    #pragma unroll
    for (int k = 0; k < 4; k++)
        asm volatile("prefetch.global.L2 [%0];" :: "l"(p + (lane * 4 + k) * 128));
}

// Warp dot over HID=4096; float4 + __ldcs (evict-first) — the proven engine.
__device__ __forceinline__ float warp_dot_row(const float4* __restrict__ w4,
                                              const float4* __restrict__ sx4,
                                              int lane) {
    float acc = 0.0f;
    #pragma unroll
    for (int i = 0; i < HID / 4 / 32; i++) {       // 32 iterations
        float4 a  = __ldcs(w4 + lane + 32 * i);
        float4 xv = sx4[lane + 32 * i];
        acc += a.x * xv.x + a.y * xv.y + a.z * xv.z + a.w * xv.w;
    }
    #pragma unroll
    for (int off = 16; off; off >>= 1)
        acc += __shfl_down_sync(0xffffffffu, acc, off);
    return acc;
}

// GRU gate pass for one float4 item.
__device__ __forceinline__ float4 gate_item4(
    const float4* gi, const float4* gh, const float4* hp4, int j4)
{
    float4 ir = gi[j4];
    float4 hr = gh[j4];
    float4 iz = gi[j4 + HID/4];
    float4 hz = gh[j4 + HID/4];
    float4 in_ = gi[j4 + 2*(HID/4)];
    float4 hn  = gh[j4 + 2*(HID/4)];
    float4 hp = hp4[j4];
    float4 h;
    {
        float r = sigmoidf_(ir.x + hr.x), z = sigmoidf_(iz.x + hz.x);
        float n = tanhf_(in_.x + r * hn.x); h.x = (1.0f - z) * n + z * hp.x;
    }
    {
        float r = sigmoidf_(ir.y + hr.y), z = sigmoidf_(iz.y + hz.y);
        float n = tanhf_(in_.y + r * hn.y); h.y = (1.0f - z) * n + z * hp.y;
    }
    {
        float r = sigmoidf_(ir.z + hr.z), z = sigmoidf_(iz.z + hz.z);
        float n = tanhf_(in_.z + r * hn.z); h.z = (1.0f - z) * n + z * hp.z;
    }
    {
        float r = sigmoidf_(ir.w + hr.w), z = sigmoidf_(iz.w + hz.w);
        float n = tanhf_(in_.w + r * hn.w); h.w = (1.0f - z) * n + z * hp.w;
    }
    return h;
}

// ---------------------------------------------------------------------------
// K1: gi0 = W_ih0 @ emb[inp] ; gh0 = W_hh0 @ h0 ; gh1 = W_hh1 @ h1 (+biases).
// ---------------------------------------------------------------------------
__global__ __launch_bounds__(256, 6) void mv3_kernel(
    const int* __restrict__ inp, const float* __restrict__ hidden,
    const float* __restrict__ emb,
    const float* __restrict__ Wih0, const float* __restrict__ Whh0,
    const float* __restrict__ Whh1,
    const float* __restrict__ bih0, const float* __restrict__ bhh0,
    const float* __restrict__ bhh1)
{
    __shared__ __align__(16) float sx[HID];
    const int warp = threadIdx.x >> 5;
    const int lane = threadIdx.x & 31;

    const int blocks_per_seg = GATES / ROWS_PER_BLOCK;   // 1536
    const int seg    = blockIdx.x / blocks_per_seg;      // 0,1,2
    const int segblk = blockIdx.x % blocks_per_seg;

    const float* W; const float* b; const float* x; float* y;
    if (seg == 0)      { W = Wih0; b = bih0; x = emb + (size_t)inp[0] * HID; y = g_gi0; }
    else if (seg == 1) { W = Whh0; b = bhh0; x = hidden;                     y = g_gh0; }
    else               { W = Whh1; b = bhh1; x = hidden + HID;               y = g_gh1; }

    for (int i = threadIdx.x; i < HID / 4; i += 256)
        ((float4*)sx)[i] = ((const float4*)x)[i];
    __syncthreads();

    const int row = segblk * ROWS_PER_BLOCK + warp;
    float acc = warp_dot_row((const float4*)(W + (size_t)row * HID),
                             (const float4*)sx, lane);
    if (lane == 0) y[row] = acc + b[row];
    cudaTriggerProgrammaticLaunchCompletion();
}

// ---------------------------------------------------------------------------
// K2: fused gate0 + mv1. Grid = 8 + 1536:
//   blocks 0..7 (wave-1 resident, so workers can't starve them): after the
//     PDL sync on mv3, compute one 512-elem slice of h0_new each; bump g_done0.
//   blocks 8..1543: prefetch W_ih1 row (useful DRAM work during mv3 drain +
//     gate slices), take a monotonic epoch ticket, spin for this epoch's 8
//     slices, then stage g_h0 and run the warp-per-row matvec.
// ---------------------------------------------------------------------------
__global__ __launch_bounds__(256, 6) void mv1_kernel(
    const float* __restrict__ Wih1, const float* __restrict__ bih1,
    const float* __restrict__ hidden, float* __restrict__ out)
{
    __shared__ __align__(16) float sx[HID];
    const int warp = threadIdx.x >> 5;
    const int lane = threadIdx.x & 31;

    if (blockIdx.x < MV1_GBLKS) {
        // ---- gate block ----
        cudaGridDependencySynchronize();      // mv3 done: gi0/gh0 ready
        const int slice = blockIdx.x;         // 0..7
        if (threadIdx.x < 128) {
            const int j4 = slice * 128 + threadIdx.x;    // 128 float4 items
            float4 h = gate_item4((const float4*)g_gi0, (const float4*)g_gh0,
                                  (const float4*)hidden, j4);
            ((float4*)g_h0)[j4] = h;
            ((float4*)(out + NVOCAB))[j4] = h;           // new_h[0]
        }
        __syncthreads();
        __threadfence();
        if (threadIdx.x == 0) atomicAdd(&g_done0, 1ULL);
        cudaTriggerProgrammaticLaunchCompletion();
        return;
    }

    // ---- worker block ----
    const int row = (blockIdx.x - MV1_GBLKS) * ROWS_PER_BLOCK + warp;
    const float* wrow = Wih1 + (size_t)row * HID;

    prefetch_row_l2(wrow, lane);          // independent of producer output
    cudaGridDependencySynchronize();

    __shared__ unsigned long long s_t;
    if (threadIdx.x == 0) s_t = atomicAdd(&g_warr0, 1ULL);
    __syncthreads();
    const unsigned long long epoch = s_t / (unsigned long long)MV1_WORKERS;
    if (threadIdx.x == 0) {
        const unsigned long long target = (epoch + 1ULL) * (unsigned long long)MV1_GBLKS;
        while (*((volatile unsigned long long*)&g_done0) < target) __nanosleep(32);
    }
    __syncthreads();
    __threadfence();                      // acquire: see all gate slices

    for (int i = threadIdx.x; i < HID / 4; i += 256)
        ((float4*)sx)[i] = ((const float4*)g_h0)[i];
    __syncthreads();

    float acc = warp_dot_row((const float4*)wrow, (const float4*)sx, lane);
    if (lane == 0) g_gi1[row] = acc + bih1[row];
    cudaTriggerProgrammaticLaunchCompletion();
}

// ---------------------------------------------------------------------------
// K3: fused gate1 + decoder. Grid = 40 (all wave-1):
//   blocks 32..39: compute one h1_new slice each after the sync; bump g_done1.
//   blocks  0..31: prefetch W_dec rows, wait for this epoch's 8 slices,
//                  then warp-per-row decoder matvec from g_h1.
// ---------------------------------------------------------------------------
__global__ __launch_bounds__(256) void dec_kernel(
    const float* __restrict__ Wdec, const float* __restrict__ bdec,
    const float* __restrict__ hidden, float* __restrict__ out)
{
    __shared__ __align__(16) float sx[HID];
    const int warp = threadIdx.x >> 5;
    const int lane = threadIdx.x & 31;

    if (blockIdx.x >= DEC_WORKERS) {
        // ---- gate block ----
        cudaGridDependencySynchronize();      // mv1 done: gi1/gh1 ready
        const int slice = blockIdx.x - DEC_WORKERS;      // 0..7
        if (threadIdx.x < 128) {
            const int j4 = slice * 128 + threadIdx.x;
            float4 h = gate_item4((const float4*)g_gi1, (const float4*)g_gh1,
                                  (const float4*)(hidden + HID), j4);
            ((float4*)g_h1)[j4] = h;
            ((float4*)(out + NVOCAB + HID))[j4] = h;     // new_h[1]
        }
        __syncthreads();
        __threadfence();
        if (threadIdx.x == 0) atomicAdd(&g_done1, 1ULL);
        return;
    }

    // ---- worker block ----
    const int row = blockIdx.x * ROWS_PER_BLOCK + warp;  // 0..255
    const float* wrow = Wdec + (size_t)row * HID;

    prefetch_row_l2(wrow, lane);          // useful work before the wait
    cudaGridDependencySynchronize();

    __shared__ unsigned long long s_t;
    if (threadIdx.x == 0) s_t = atomicAdd(&g_warr1, 1ULL);
    __syncthreads();
    const unsigned long long epoch = s_t / (unsigned long long)DEC_WORKERS;
    if (threadIdx.x == 0) {
        const unsigned long long target = (epoch + 1ULL) * (unsigned long long)DEC_GATES;
        while (*((volatile unsigned long long*)&g_done1) < target) __nanosleep(32);
    }
    __syncthreads();
    __threadfence();                      // acquire: see all gate slices

    for (int i = threadIdx.x; i < HID / 4; i += 256)
        ((float4*)sx)[i] = ((const float4*)g_h1)[i];
    __syncthreads();

    float acc = warp_dot_row((const float4*)wrow, (const float4*)sx, lane);
    if (lane == 0) out[row] = acc + bdec[row];
}

// ---------------------------------------------------------------------------
// Inputs (metadata order):
// 0 inp(int32,1) 1 hidden(2*4096) 2 emb(256*4096)
// 3 W_ih0 4 W_hh0 5 b_ih0 6 b_hh0
// 7 W_ih1 8 W_hh1 9 b_ih1 10 b_hh1
// 11 W_dec 12 b_dec
// Output: [logits(256) | h0_new(4096) | h1_new(4096)]
// ---------------------------------------------------------------------------
template <typename... Args>
static inline void launch_pdl(void (*kern)(Args...), dim3 grid, dim3 block,
                              Args... args)
{
    cudaLaunchConfig_t cfg = {};
    cfg.gridDim = grid;
    cfg.blockDim = block;
    cfg.dynamicSmemBytes = 0;
    cfg.stream = 0;
    cudaLaunchAttribute attr[1];
    attr[0].id = cudaLaunchAttributeProgrammaticStreamSerialization;
    attr[0].val.programmaticStreamSerializationAllowed = 1;
    cfg.attrs = attr;
    cfg.numAttrs = 1;
    cudaLaunchKernelEx(&cfg, kern, args...);
}

extern "C" void kernel_launch(void* const* d_in, const int* in_sizes, int n_in,
                              void* d_out, int out_size)
{
    const int*   inp    = (const int*)  d_in[0];
    const float* hidden = (const float*)d_in[1];
    const float* emb    = (const float*)d_in[2];
    const float* Wih0   = (const float*)d_in[3];
    const float* Whh0   = (const float*)d_in[4];
    const float* bih0   = (const float*)d_in[5];
    const float* bhh0   = (const float*)d_in[6];
    const float* Wih1   = (const float*)d_in[7];
    const float* Whh1   = (const float*)d_in[8];
    const float* bih1   = (const float*)d_in[9];
    const float* bhh1   = (const float*)d_in[10];
    const float* Wdec   = (const float*)d_in[11];
    const float* bdec   = (const float*)d_in[12];
    float* out = (float*)d_out;

    mv3_kernel<<<3 * (GATES / ROWS_PER_BLOCK), 256>>>(inp, hidden, emb,
                                                      Wih0, Whh0, Whh1,
                                                      bih0, bhh0, bhh1);
    launch_pdl(mv1_kernel, dim3(MV1_GBLKS + MV1_WORKERS), dim3(256),
               Wih1, bih1, hidden, out);
    launch_pdl(dec_kernel, dim3(DEC_WORKERS + DEC_GATES), dim3(256),
               Wdec, bdec, hidden, out);
}

// round 16
// speedup vs baseline: 1.0250x; 1.0250x over previous
#include <cuda_runtime.h>

#define HID 4096
#define GATES (3*HID)
#define NVOCAB 256
#define ROWS_PER_BLOCK 8     // 8 warps, warp-per-row
#define SEG_BLOCKS (GATES / ROWS_PER_BLOCK)  // 1536 blocks per matrix
#define MV1_GBLKS 8          // mv1: blocks 0-7 compute gate0 slices
#define DEC_WORKERS 32       // dec: blocks 0-31 decoder rows
#define DEC_GATES 8          // dec: blocks 32-39 gate1 slices

// Scratch (allocation-free rule: __device__ globals). 16B-aligned for float4.
__device__ __align__(16) float g_gi0[GATES];
__device__ __align__(16) float g_gh0[GATES];
__device__ __align__(16) float g_gh1[GATES];
__device__ __align__(16) float g_gi1[GATES];
__device__ __align__(16) float g_h0[HID];
__device__ __align__(16) float g_h1[HID];
// Replay-safe monotonic counters (never reset; epochs via division).
__device__ unsigned long long g_done0;   // +8 per replay    (mv1 gate blocks)
__device__ unsigned long long g_warr0;   // +1536 per replay (mv1 W_ih1 tickets)
__device__ unsigned long long g_done1;   // +8 per replay    (dec gate blocks)
__device__ unsigned long long g_warr1;   // +32 per replay   (dec worker tickets)

__device__ __forceinline__ float sigmoidf_(float v) {
    return __fdividef(1.0f, 1.0f + __expf(-v));
}
__device__ __forceinline__ float tanhf_(float v) {
    return __fdividef(2.0f, 1.0f + __expf(-2.0f * v)) - 1.0f;
}

// Prefetch this warp's 16KB weight row into L2 (4 x 128B lines per lane).
__device__ __forceinline__ void prefetch_row_l2(const float* wrow, int lane) {
    const char* p = (const char*)wrow;
    #pragma unroll
    for (int k = 0; k < 4; k++)
        asm volatile("prefetch.global.L2 [%0];" :: "l"(p + (lane * 4 + k) * 128));
}

// Warp dot over HID=4096; float4 + __ldcs (evict-first) — the proven engine.
__device__ __forceinline__ float warp_dot_row(const float4* __restrict__ w4,
                                              const float4* __restrict__ sx4,
                                              int lane) {
    float acc = 0.0f;
    #pragma unroll
    for (int i = 0; i < HID / 4 / 32; i++) {       // 32 iterations
        float4 a  = __ldcs(w4 + lane + 32 * i);
        float4 xv = sx4[lane + 32 * i];
        acc += a.x * xv.x + a.y * xv.y + a.z * xv.z + a.w * xv.w;
    }
    #pragma unroll
    for (int off = 16; off; off >>= 1)
        acc += __shfl_down_sync(0xffffffffu, acc, off);
    return acc;
}

// GRU gate pass for one float4 item.
__device__ __forceinline__ float4 gate_item4(
    const float4* gi, const float4* gh, const float4* hp4, int j4)
{
    float4 ir = gi[j4];
    float4 hr = gh[j4];
    float4 iz = gi[j4 + HID/4];
    float4 hz = gh[j4 + HID/4];
    float4 in_ = gi[j4 + 2*(HID/4)];
    float4 hn  = gh[j4 + 2*(HID/4)];
    float4 hp = hp4[j4];
    float4 h;
    {
        float r = sigmoidf_(ir.x + hr.x), z = sigmoidf_(iz.x + hz.x);
        float n = tanhf_(in_.x + r * hn.x); h.x = (1.0f - z) * n + z * hp.x;
    }
    {
        float r = sigmoidf_(ir.y + hr.y), z = sigmoidf_(iz.y + hz.y);
        float n = tanhf_(in_.y + r * hn.y); h.y = (1.0f - z) * n + z * hp.y;
    }
    {
        float r = sigmoidf_(ir.z + hr.z), z = sigmoidf_(iz.z + hz.z);
        float n = tanhf_(in_.z + r * hn.z); h.z = (1.0f - z) * n + z * hp.z;
    }
    {
        float r = sigmoidf_(ir.w + hr.w), z = sigmoidf_(iz.w + hz.w);
        float n = tanhf_(in_.w + r * hn.w); h.w = (1.0f - z) * n + z * hp.w;
    }
    return h;
}

// ---------------------------------------------------------------------------
// K1: gi0 = W_ih0 @ emb[inp] ; gh0 = W_hh0 @ h0 (+biases). 402 MB, 3072 blks.
// (W_hh1 migrated into K2 where it overlaps gate0.)
// ---------------------------------------------------------------------------
__global__ __launch_bounds__(256, 6) void mv3_kernel(
    const int* __restrict__ inp, const float* __restrict__ hidden,
    const float* __restrict__ emb,
    const float* __restrict__ Wih0, const float* __restrict__ Whh0,
    const float* __restrict__ bih0, const float* __restrict__ bhh0)
{
    __shared__ __align__(16) float sx[HID];
    const int warp = threadIdx.x >> 5;
    const int lane = threadIdx.x & 31;

    const int seg    = blockIdx.x / SEG_BLOCKS;      // 0,1
    const int segblk = blockIdx.x % SEG_BLOCKS;

    const float* W; const float* b; const float* x; float* y;
    if (seg == 0) { W = Wih0; b = bih0; x = emb + (size_t)inp[0] * HID; y = g_gi0; }
    else          { W = Whh0; b = bhh0; x = hidden;                     y = g_gh0; }

    for (int i = threadIdx.x; i < HID / 4; i += 256)
        ((float4*)sx)[i] = ((const float4*)x)[i];
    __syncthreads();

    const int row = segblk * ROWS_PER_BLOCK + warp;
    float acc = warp_dot_row((const float4*)(W + (size_t)row * HID),
                             (const float4*)sx, lane);
    if (lane == 0) y[row] = acc + b[row];
    cudaTriggerProgrammaticLaunchCompletion();
}

// ---------------------------------------------------------------------------
// K2: three roles, grid = 8 + 1536 + 1536 = 3080:
//   blocks 0..7:        gate0 slices (sync on mv3, then h0_new; bump g_done0)
//   blocks 8..1543:     W_hh1 streamers — gh1 = W_hh1 @ h1 + b_hh1. Depend
//                       ONLY on kernel inputs: no grid sync, stream instantly,
//                       keeping DRAM busy through the gate0 window.
//   blocks 1544..3079:  W_ih1 workers — prefetch row, sync on mv3, wait for
//                       this epoch's 8 gate slices (near-zero: they arrive in
//                       later waves), then gi1 = W_ih1 @ h0_new + b_ih1.
// ---------------------------------------------------------------------------
__global__ __launch_bounds__(256, 6) void mv1_kernel(
    const float* __restrict__ Wih1, const float* __restrict__ Whh1,
    const float* __restrict__ bih1, const float* __restrict__ bhh1,
    const float* __restrict__ hidden, float* __restrict__ out)
{
    __shared__ __align__(16) float sx[HID];
    const int warp = threadIdx.x >> 5;
    const int lane = threadIdx.x & 31;

    if (blockIdx.x < MV1_GBLKS) {
        // ---- gate0 slice block ----
        cudaGridDependencySynchronize();      // mv3 done: gi0/gh0 ready
        const int slice = blockIdx.x;         // 0..7
        if (threadIdx.x < 128) {
            const int j4 = slice * 128 + threadIdx.x;    // 128 float4 items
            float4 h = gate_item4((const float4*)g_gi0, (const float4*)g_gh0,
                                  (const float4*)hidden, j4);
            ((float4*)g_h0)[j4] = h;
            ((float4*)(out + NVOCAB))[j4] = h;           // new_h[0]
        }
        __syncthreads();
        __threadfence();
        if (threadIdx.x == 0) atomicAdd(&g_done0, 1ULL);
        cudaTriggerProgrammaticLaunchCompletion();
        return;
    }

    if (blockIdx.x < MV1_GBLKS + SEG_BLOCKS) {
        // ---- W_hh1 streamer: inputs only, no sync, stream immediately ----
        const int row = (blockIdx.x - MV1_GBLKS) * ROWS_PER_BLOCK + warp;
        for (int i = threadIdx.x; i < HID / 4; i += 256)
            ((float4*)sx)[i] = ((const float4*)(hidden + HID))[i];
        __syncthreads();
        float acc = warp_dot_row((const float4*)(Whh1 + (size_t)row * HID),
                                 (const float4*)sx, lane);
        if (lane == 0) g_gh1[row] = acc + bhh1[row];
        cudaTriggerProgrammaticLaunchCompletion();
        return;
    }

    // ---- W_ih1 worker ----
    const int row = (blockIdx.x - MV1_GBLKS - SEG_BLOCKS) * ROWS_PER_BLOCK + warp;
    const float* wrow = Wih1 + (size_t)row * HID;

    prefetch_row_l2(wrow, lane);          // independent of producer output
    cudaGridDependencySynchronize();

    __shared__ unsigned long long s_t;
    if (threadIdx.x == 0) s_t = atomicAdd(&g_warr0, 1ULL);
    __syncthreads();
    const unsigned long long epoch = s_t / (unsigned long long)SEG_BLOCKS;
    if (threadIdx.x == 0) {
        const unsigned long long target = (epoch + 1ULL) * (unsigned long long)MV1_GBLKS;
        while (*((volatile unsigned long long*)&g_done0) < target) __nanosleep(32);
    }
    __syncthreads();
    __threadfence();                      // acquire: see all gate slices

    for (int i = threadIdx.x; i < HID / 4; i += 256)
        ((float4*)sx)[i] = ((const float4*)g_h0)[i];
    __syncthreads();

    float acc = warp_dot_row((const float4*)wrow, (const float4*)sx, lane);
    if (lane == 0) g_gi1[row] = acc + bih1[row];
    cudaTriggerProgrammaticLaunchCompletion();
}

// ---------------------------------------------------------------------------
// K3: fused gate1 + decoder. Grid = 40 (all wave-1):
//   blocks 32..39: one h1_new slice each after the sync; bump g_done1.
//   blocks  0..31: prefetch W_dec rows, wait for this epoch's 8 slices,
//                  then warp-per-row decoder matvec from g_h1.
// ---------------------------------------------------------------------------
__global__ __launch_bounds__(256) void dec_kernel(
    const float* __restrict__ Wdec, const float* __restrict__ bdec,
    const float* __restrict__ hidden, float* __restrict__ out)
{
    __shared__ __align__(16) float sx[HID];
    const int warp = threadIdx.x >> 5;
    const int lane = threadIdx.x & 31;

    if (blockIdx.x >= DEC_WORKERS) {
        // ---- gate1 slice block ----
        cudaGridDependencySynchronize();      // mv1 done: gi1/gh1 ready
        const int slice = blockIdx.x - DEC_WORKERS;      // 0..7
        if (threadIdx.x < 128) {
            const int j4 = slice * 128 + threadIdx.x;
            float4 h = gate_item4((const float4*)g_gi1, (const float4*)g_gh1,
                                  (const float4*)(hidden + HID), j4);
            ((float4*)g_h1)[j4] = h;
            ((float4*)(out + NVOCAB + HID))[j4] = h;     // new_h[1]
        }
        __syncthreads();
        __threadfence();
        if (threadIdx.x == 0) atomicAdd(&g_done1, 1ULL);
        return;
    }

    // ---- worker block ----
    const int row = blockIdx.x * ROWS_PER_BLOCK + warp;  // 0..255
    const float* wrow = Wdec + (size_t)row * HID;

    prefetch_row_l2(wrow, lane);          // useful work before the wait
    cudaGridDependencySynchronize();

    __shared__ unsigned long long s_t;
    if (threadIdx.x == 0) s_t = atomicAdd(&g_warr1, 1ULL);
    __syncthreads();
    const unsigned long long epoch = s_t / (unsigned long long)DEC_WORKERS;
    if (threadIdx.x == 0) {
        const unsigned long long target = (epoch + 1ULL) * (unsigned long long)DEC_GATES;
        while (*((volatile unsigned long long*)&g_done1) < target) __nanosleep(32);
    }
    __syncthreads();
    __threadfence();                      // acquire: see all gate slices

    for (int i = threadIdx.x; i < HID / 4; i += 256)
        ((float4*)sx)[i] = ((const float4*)g_h1)[i];
    __syncthreads();

    float acc = warp_dot_row((const float4*)wrow, (const float4*)sx, lane);
    if (lane == 0) out[row] = acc + bdec[row];
}

// ---------------------------------------------------------------------------
// Inputs (metadata order):
// 0 inp(int32,1) 1 hidden(2*4096) 2 emb(256*4096)
// 3 W_ih0 4 W_hh0 5 b_ih0 6 b_hh0
// 7 W_ih1 8 W_hh1 9 b_ih1 10 b_hh1
// 11 W_dec 12 b_dec
// Output: [logits(256) | h0_new(4096) | h1_new(4096)]
// ---------------------------------------------------------------------------
template <typename... Args>
static inline void launch_pdl(void (*kern)(Args...), dim3 grid, dim3 block,
                              Args... args)
{
    cudaLaunchConfig_t cfg = {};
    cfg.gridDim = grid;
    cfg.blockDim = block;
    cfg.dynamicSmemBytes = 0;
    cfg.stream = 0;
    cudaLaunchAttribute attr[1];
    attr[0].id = cudaLaunchAttributeProgrammaticStreamSerialization;
    attr[0].val.programmaticStreamSerializationAllowed = 1;
    cfg.attrs = attr;
    cfg.numAttrs = 1;
    cudaLaunchKernelEx(&cfg, kern, args...);
}

extern "C" void kernel_launch(void* const* d_in, const int* in_sizes, int n_in,
                              void* d_out, int out_size)
{
    const int*   inp    = (const int*)  d_in[0];
    const float* hidden = (const float*)d_in[1];
    const float* emb    = (const float*)d_in[2];
    const float* Wih0   = (const float*)d_in[3];
    const float* Whh0   = (const float*)d_in[4];
    const float* bih0   = (const float*)d_in[5];
    const float* bhh0   = (const float*)d_in[6];
    const float* Wih1   = (const float*)d_in[7];
    const float* Whh1   = (const float*)d_in[8];
    const float* bih1   = (const float*)d_in[9];
    const float* bhh1   = (const float*)d_in[10];
    const float* Wdec   = (const float*)d_in[11];
    const float* bdec   = (const float*)d_in[12];
    float* out = (float*)d_out;

    mv3_kernel<<<2 * SEG_BLOCKS, 256>>>(inp, hidden, emb, Wih0, Whh0,
                                        bih0, bhh0);
    launch_pdl(mv1_kernel, dim3(MV1_GBLKS + 2 * SEG_BLOCKS), dim3(256),
               Wih1, Whh1, bih1, bhh1, hidden, out);
    launch_pdl(dec_kernel, dim3(DEC_WORKERS + DEC_GATES), dim3(256),
               Wdec, bdec, hidden, out);
}